// round 3
// baseline (speedup 1.0000x reference)
#include <cuda_runtime.h>

// B=32, S=12, F=128, K=8, H=64, C=64, N=512
#define BB   32
#define SEQ  12
#define FF   128
#define KK   8
#define HH   64
#define CC   64
#define NNN  512
#define NCH  8                      // Wf n-chunks (64 n each)
#define NBLK (KK + CC * NCH)        // 8 + 512 = 520 blocks
#define TPB  256

// Scratch + sync (allocation-free rule: __device__ globals)
__device__ float g_hcat[BB * KK * HH];       // 32 x 512: elu(Wh_row)
__device__ float g_part[NCH * CC * CC];      // [p][c][c'] transposed partial Wf sums
__device__ unsigned int g_ctr = 0;           // monotonic across graph replays

__global__ void __launch_bounds__(TPB, 4) gat_fused(
    const float* __restrict__ x,        // (32,12,128)
    const float* __restrict__ W_heads,  // (8,128,64)
    const float* __restrict__ W_out,    // (512,64)
    const float* __restrict__ Wf,       // (64, 512*64)
    const float* __restrict__ bf,       // (64,)
    float* __restrict__ out)            // (32,64)
{
    __shared__ float smem[6144];        // 24 KB, reused across phases
    const int blk = blockIdx.x;
    const int t   = threadIdx.x;

    // ================= Phase A =================
    if (blk < KK) {
        // ---- head-k GEMM: Wh[b,h] = x_row[b,:] @ W_heads[k,:,:], then elu ----
        const int k = blk;
        float*  s_x = smem;                       // 32*128 = 4096 floats
        float4* sW4 = (float4*)(smem + 4096);     // 32*64  = 2048 floats = 512 f4

        for (int i = t; i < BB * FF; i += TPB)
            s_x[i] = x[(i >> 7) * (SEQ * FF) + (SEQ - 1) * FF + (i & 127)];

        const int h4 = t & 15;        // h = 4*h4 .. 4*h4+3
        const int bp = t >> 4;        // b in {bp, bp+16}
        float4 a0 = make_float4(0.f, 0.f, 0.f, 0.f);
        float4 a1 = make_float4(0.f, 0.f, 0.f, 0.f);
        const float4* Wg = (const float4*)(W_heads + (size_t)k * FF * HH);

        for (int ft = 0; ft < 4; ++ft) {          // f tiles of 32
            __syncthreads();
            sW4[t]       = Wg[ft * 512 + t];
            sW4[t + 256] = Wg[ft * 512 + t + 256];
            __syncthreads();
            #pragma unroll
            for (int fl = 0; fl < 32; ++fl) {
                const int f = ft * 32 + fl;
                const float4 w = sW4[fl * 16 + h4];
                const float xa = s_x[bp * FF + f];
                const float xb = s_x[(bp + 16) * FF + f];
                a0.x = fmaf(w.x, xa, a0.x); a0.y = fmaf(w.y, xa, a0.y);
                a0.z = fmaf(w.z, xa, a0.z); a0.w = fmaf(w.w, xa, a0.w);
                a1.x = fmaf(w.x, xb, a1.x); a1.y = fmaf(w.y, xb, a1.y);
                a1.z = fmaf(w.z, xb, a1.z); a1.w = fmaf(w.w, xb, a1.w);
            }
        }
        // elu + store (float4, hcat index = b*512 + k*64 + 4*h4)
        float4 r;
        r.x = a0.x > 0.f ? a0.x : expm1f(a0.x);
        r.y = a0.y > 0.f ? a0.y : expm1f(a0.y);
        r.z = a0.z > 0.f ? a0.z : expm1f(a0.z);
        r.w = a0.w > 0.f ? a0.w : expm1f(a0.w);
        ((float4*)g_hcat)[bp * 128 + k * 16 + h4] = r;
        r.x = a1.x > 0.f ? a1.x : expm1f(a1.x);
        r.y = a1.y > 0.f ? a1.y : expm1f(a1.y);
        r.z = a1.z > 0.f ? a1.z : expm1f(a1.z);
        r.w = a1.w > 0.f ? a1.w : expm1f(a1.w);
        ((float4*)g_hcat)[(bp + 16) * 128 + k * 16 + h4] = r;
    } else {
        // ---- Wf partial reduce: row cp, n-chunk p (64 n's = 16 KB) ----
        const int idx = blk - KK;
        const int cp  = idx >> 3;
        const int p   = idx & 7;
        const float4* src = (const float4*)(Wf + (size_t)cp * (NNN * CC) + p * (64 * CC));
        const int c4 = t & 15;        // float4 column (c = 4*c4..)
        const int nl = t >> 4;        // 0..15
        float4 a = make_float4(0.f, 0.f, 0.f, 0.f);
        #pragma unroll
        for (int j = 0; j < 4; ++j) {
            const float4 v = src[(nl + 16 * j) * 16 + c4];
            a.x += v.x; a.y += v.y; a.z += v.z; a.w += v.w;
        }
        float4* s4 = (float4*)smem;
        s4[t] = a;
        __syncthreads();
        if (t < 128) { float4 o = s4[t + 128]; s4[t].x += o.x; s4[t].y += o.y; s4[t].z += o.z; s4[t].w += o.w; }
        __syncthreads();
        if (t < 64)  { float4 o = s4[t + 64];  s4[t].x += o.x; s4[t].y += o.y; s4[t].z += o.z; s4[t].w += o.w; }
        __syncthreads();
        if (t < 16) {
            float4 r2 = s4[t];
            float4 o1 = s4[t + 16], o2 = s4[t + 32], o3 = s4[t + 48];
            r2.x += o1.x + o2.x + o3.x;
            r2.y += o1.y + o2.y + o3.y;
            r2.z += o1.z + o2.z + o3.z;
            r2.w += o1.w + o2.w + o3.w;
            // transposed store: g_part[p][c][cp]
            const int base = p * (CC * CC) + (4 * t) * CC + cp;
            g_part[base         ] = r2.x;
            g_part[base +     CC] = r2.y;
            g_part[base + 2 * CC] = r2.z;
            g_part[base + 3 * CC] = r2.w;
        }
    }

    // ================= Grid barrier =================
    __threadfence();
    __syncthreads();
    __shared__ unsigned int s_tk;
    if (t == 0) s_tk = atomicAdd(&g_ctr, 1u);
    __syncthreads();
    if (blk >= BB) return;                 // producers arrived; only 32 consumers spin
    if (t == 0) {
        const unsigned int target = (s_tk / NBLK + 1u) * NBLK;
        volatile unsigned int* pc = &g_ctr;
        while (*pc < target) { }
    }
    __syncthreads();
    __threadfence();

    // ================= Phase B (blocks 0..31, one batch each) =================
    const int b = blk;
    float*  s_h   = smem;                         // 512
    float4* s4    = (float4*)(smem + 512);        // 256 f4 = 1024 floats
    float*  s_WhO = smem + 512 + 1024;            // 64

    for (int i = t; i < KK * HH; i += TPB) s_h[i] = g_hcat[b * (KK * HH) + i];
    __syncthreads();

    // WhO[c] = sum_j hcat[j] * W_out[j,c]   (zero-redundancy float4 over c)
    {
        const int c4 = t & 15;
        const int g  = t >> 4;                    // 16 j-groups of 32
        const float4* Wo4 = (const float4*)W_out;
        float4 a = make_float4(0.f, 0.f, 0.f, 0.f);
        #pragma unroll 8
        for (int jl = 0; jl < 32; ++jl) {
            const int j = g * 32 + jl;
            const float4 w = Wo4[j * 16 + c4];
            const float hv = s_h[j];
            a.x = fmaf(w.x, hv, a.x); a.y = fmaf(w.y, hv, a.y);
            a.z = fmaf(w.z, hv, a.z); a.w = fmaf(w.w, hv, a.w);
        }
        s4[t] = a;
        __syncthreads();
        if (t < 128) { float4 o = s4[t + 128]; s4[t].x += o.x; s4[t].y += o.y; s4[t].z += o.z; s4[t].w += o.w; }
        __syncthreads();
        if (t < 64)  { float4 o = s4[t + 64];  s4[t].x += o.x; s4[t].y += o.y; s4[t].z += o.z; s4[t].w += o.w; }
        __syncthreads();
        if (t < 32)  { float4 o = s4[t + 32];  s4[t].x += o.x; s4[t].y += o.y; s4[t].z += o.z; s4[t].w += o.w; }
        __syncthreads();
        if (t < 16) {
            float4 r2 = s4[t], o = s4[t + 16];
            s_WhO[4 * t + 0] = r2.x + o.x;
            s_WhO[4 * t + 1] = r2.y + o.y;
            s_WhO[4 * t + 2] = r2.z + o.z;
            s_WhO[4 * t + 3] = r2.w + o.w;
        }
        __syncthreads();
    }

    // final[b,c'] = bf[c'] + sum_c WhO[c] * sum_p part[p][c][c']
    {
        const int cpr = t & 63;
        const int pg  = t >> 6;                   // handles p = 2pg, 2pg+1
        float fa = 0.f;
        #pragma unroll
        for (int pp = 0; pp < 2; ++pp) {
            const float* pb = g_part + (pg * 2 + pp) * (CC * CC) + cpr;
            #pragma unroll 8
            for (int cc = 0; cc < CC; ++cc)
                fa = fmaf(s_WhO[cc], pb[cc * CC], fa);
        }
        float* s_fp = smem;                       // reuse (s_h no longer read)
        s_fp[t] = fa;
        __syncthreads();
        if (t < CC)
            out[b * CC + t] = bf[t] + s_fp[t] + s_fp[t + 64] + s_fp[t + 128] + s_fp[t + 192];
    }
}

extern "C" void kernel_launch(void* const* d_in, const int* in_sizes, int n_in,
                              void* d_out, int out_size)
{
    const float* x       = (const float*)d_in[0];
    const float* W_heads = (const float*)d_in[1];
    // d_in[2], d_in[3]: a1_heads/a2_heads — drop out (uniform softmax)
    const float* W_out   = (const float*)d_in[4];
    // d_in[5], d_in[6]: a1_out/a2_out — drop out
    const float* Wf      = (const float*)d_in[7];
    const float* bf      = (const float*)d_in[8];
    float* out           = (float*)d_out;

    gat_fused<<<NBLK, TPB>>>(x, W_heads, W_out, Wf, bf, out);
}

// round 4
// speedup vs baseline: 1.1313x; 1.1313x over previous
#include <cuda_runtime.h>

// B=32, S=12, F=128, K=8, H=64, C=64, N=512
#define BB    32
#define SEQ   12
#define FF    128
#define KK    8
#define HH    64
#define CC    64
#define NNN   512
#define NCH   4                       // Wf n-chunks per row (128 n = 32KB each)
#define NPROD BB                      // 32 producer blocks
#define NCONS (CC * NCH)              // 256 consumer blocks
#define NBLK  (NPROD + NCONS)         // 288
#define TPB   256

// Scratch + sync (allocation-free rule: __device__ globals)
__device__ float g_WhO[BB * CC];          // second-layer rows (32 x 64)
__device__ unsigned int g_tick = 0;       // epoch tickets (monotonic across replays)
__device__ unsigned int g_done = 0;       // producer-done count (monotonic)

__global__ void __launch_bounds__(TPB, 4) gat_fused(
    const float* __restrict__ x,        // (32,12,128)
    const float* __restrict__ W_heads,  // (8,128,64)
    const float* __restrict__ W_out,    // (512,64)
    const float* __restrict__ Wf,       // (64, 512*64)
    const float* __restrict__ bf,       // (64,)
    float* __restrict__ out)            // (32,64)
{
    __shared__ float smem[3200];          // 12.8 KB, reused per role
    __shared__ unsigned int s_epoch;
    const int blk = blockIdx.x;
    const int t   = threadIdx.x;

    if (t == 0) s_epoch = atomicAdd(&g_tick, 1u) / NBLK;

    if (blk < NPROD) {
        // ================= Producer: one batch b =================
        const int b = blk;
        float* s_x    = smem;             // 128
        float* s_hcat = smem + 128;       // 512
        float4* s4    = (float4*)(smem + 640);   // 256 f4 = 1024 floats

        if (t < FF) s_x[t] = x[b * SEQ * FF + (SEQ - 1) * FF + t];
        __syncthreads();

        // hcat[k*64+h] = elu( sum_f x[f] * W_heads[k,f,h] ); 2 outputs/thread (k, k+4)
        {
            const int o  = t;                       // k = o>>6 in 0..3, h = o&63
            const float* w1 = W_heads + (size_t)(o >> 6) * FF * HH + (o & 63);
            const float* w2 = w1 + 4 * FF * HH;     // k+4
            float a0 = 0.f, a1 = 0.f;
            #pragma unroll 8
            for (int f = 0; f < FF; ++f) {
                const float xv = s_x[f];
                a0 = fmaf(xv, w1[f * HH], a0);
                a1 = fmaf(xv, w2[f * HH], a1);
            }
            s_hcat[o]       = a0 > 0.f ? a0 : expm1f(a0);
            s_hcat[o + 256] = a1 > 0.f ? a1 : expm1f(a1);
        }
        __syncthreads();

        // WhO[c] = sum_j hcat[j] * W_out[j,c]  (float4 over c, 16 j-groups)
        {
            const int c4 = t & 15;
            const int g  = t >> 4;
            const float4* Wo4 = (const float4*)W_out;
            float4 a = make_float4(0.f, 0.f, 0.f, 0.f);
            #pragma unroll 8
            for (int jl = 0; jl < 32; ++jl) {
                const int j = g * 32 + jl;
                const float4 w = Wo4[j * 16 + c4];
                const float hv = s_hcat[j];
                a.x = fmaf(w.x, hv, a.x); a.y = fmaf(w.y, hv, a.y);
                a.z = fmaf(w.z, hv, a.z); a.w = fmaf(w.w, hv, a.w);
            }
            s4[t] = a;
            __syncthreads();
            if (t < 128) { float4 o = s4[t + 128]; s4[t].x += o.x; s4[t].y += o.y; s4[t].z += o.z; s4[t].w += o.w; }
            __syncthreads();
            if (t < 64)  { float4 o = s4[t + 64];  s4[t].x += o.x; s4[t].y += o.y; s4[t].z += o.z; s4[t].w += o.w; }
            __syncthreads();
            if (t < 16) {
                float4 r = s4[t];
                float4 o1 = s4[t + 16], o2 = s4[t + 32], o3 = s4[t + 48];
                r.x += o1.x + o2.x + o3.x;
                r.y += o1.y + o2.y + o3.y;
                r.z += o1.z + o2.z + o3.z;
                r.w += o1.w + o2.w + o3.w;
                ((float4*)(g_WhO + b * CC))[t] = r;
            }
            __syncthreads();
            if (t < CC) out[b * CC + t] = bf[t];   // init; consumers accumulate on top
        }

        // publish
        __threadfence();
        __syncthreads();
        if (t == 0) atomicAdd(&g_done, 1u);
    } else {
        // ================= Consumer: Wf chunk (cp, p) =================
        const int idx = blk - NPROD;
        const int cp  = idx >> 2;           // output column c' (0..63)
        const int p   = idx & 3;            // n-chunk (128 n's, 32KB)
        const float4* src4 = (const float4*)(Wf + (size_t)cp * (NNN * CC) + p * (128 * CC));
        const int c4 = t & 15;              // float4 column within 64 c's
        const int nl = t >> 4;              // 0..15

        // stream 8 independent LDG.128 per thread (MLP=8)
        float4 a = make_float4(0.f, 0.f, 0.f, 0.f);
        #pragma unroll
        for (int j = 0; j < 8; ++j) {
            const float4 v = src4[(nl + 16 * j) * 16 + c4];
            a.x += v.x; a.y += v.y; a.z += v.z; a.w += v.w;
        }

        float4* s4      = (float4*)smem;          // 256 f4 = 4KB
        float*  s_wpart = smem + 1024;            // 64
        float*  s_WhO   = smem + 1088;            // 2048 floats

        s4[t] = a;
        __syncthreads();
        if (t < 128) { float4 o = s4[t + 128]; s4[t].x += o.x; s4[t].y += o.y; s4[t].z += o.z; s4[t].w += o.w; }
        __syncthreads();
        if (t < 64)  { float4 o = s4[t + 64];  s4[t].x += o.x; s4[t].y += o.y; s4[t].z += o.z; s4[t].w += o.w; }
        __syncthreads();
        if (t < 16) {
            float4 r = s4[t];
            float4 o1 = s4[t + 16], o2 = s4[t + 32], o3 = s4[t + 48];
            s_wpart[4 * t + 0] = r.x + o1.x + o2.x + o3.x;
            s_wpart[4 * t + 1] = r.y + o1.y + o2.y + o3.y;
            s_wpart[4 * t + 2] = r.z + o1.z + o2.z + o3.z;
            s_wpart[4 * t + 3] = r.w + o1.w + o2.w + o3.w;
        }
        __syncthreads();

        // wait for all 32 producers of this epoch
        if (t == 0) {
            const unsigned int target = (s_epoch + 1u) * NPROD;
            volatile unsigned int* pd = &g_done;
            while (*pd < target) { }
        }
        __syncthreads();
        __threadfence();

        // copy WhO (8KB, L2-hot, coalesced)
        {
            float4* d = (float4*)s_WhO;
            const float4* s = (const float4*)g_WhO;
            d[t] = s[t];
            d[t + 256] = s[t + 256];
        }
        __syncthreads();

        // contrib[b] = sum_c WhO[b,c] * wpart[c]; 8 threads per b
        {
            const int b  = t >> 3;              // 0..31
            const int jg = t & 7;
            float acc = 0.f;
            #pragma unroll
            for (int i = 0; i < 8; ++i) {
                const int c = jg * 8 + i;
                acc = fmaf(s_WhO[b * CC + c], s_wpart[c], acc);
            }
            acc += __shfl_down_sync(0xffffffffu, acc, 4);
            acc += __shfl_down_sync(0xffffffffu, acc, 2);
            acc += __shfl_down_sync(0xffffffffu, acc, 1);
            if (jg == 0) atomicAdd(&out[b * CC + cp], acc);
        }
    }
}

extern "C" void kernel_launch(void* const* d_in, const int* in_sizes, int n_in,
                              void* d_out, int out_size)
{
    const float* x       = (const float*)d_in[0];
    const float* W_heads = (const float*)d_in[1];
    // d_in[2], d_in[3]: a1_heads/a2_heads — drop out (uniform softmax)
    const float* W_out   = (const float*)d_in[4];
    // d_in[5], d_in[6]: a1_out/a2_out — drop out
    const float* Wf      = (const float*)d_in[7];
    const float* bf      = (const float*)d_in[8];
    float* out           = (float*)d_out;

    gat_fused<<<NBLK, TPB>>>(x, W_heads, W_out, Wf, bf, out);
}

// round 8
// speedup vs baseline: 1.6375x; 1.4475x over previous
#include <cuda_runtime.h>

// B=32, S=12, F=128, K=8, H=64, C=64, N=512
#define BB    32
#define SEQ   12
#define FF    128
#define KK    8
#define HH    64
#define CC    64
#define NNN   512
#define NCONS 256                    // consumer blocks: (b,k) for stage1 AND (cp,p) for Wf
#define NST2  32                     // stage-2 blocks (one batch each)
#define NBLK  (NCONS + NST2)         // 288 <= 296 resident slots @ 2/SM
#define TPB   256

// Scratch + sync (allocation-free rule: __device__ globals)
__device__ float g_hcat[BB * KK * HH];    // 32 x 512 elu(Wh_row)
__device__ float g_WhO[BB * CC];          // 32 x 64
__device__ unsigned int g_tick = 0;       // epoch tickets (monotonic across replays)
__device__ unsigned int g_d1 = 0;         // stage-1 done count
__device__ unsigned int g_d2 = 0;         // stage-2 done count

__device__ __forceinline__ void spin_until(volatile unsigned int* p, unsigned int target)
{
    while (*p < target) { __nanosleep(64); }
}

__global__ void __launch_bounds__(TPB, 2) gat_fused(
    const float* __restrict__ x,        // (32,12,128)
    const float* __restrict__ W_heads,  // (8,128,64)
    const float* __restrict__ W_out,    // (512,64)
    const float* __restrict__ Wf,       // (64, 512*64)
    const float* __restrict__ bf,       // (64,)
    float* __restrict__ out)            // (32,64)
{
    __shared__ float smem[3136];          // 12.5 KB, region-reused with syncs between
    __shared__ unsigned int s_epoch;      // written+read by t==0 only
    const int blk = blockIdx.x;
    const int t   = threadIdx.x;

    if (t == 0) s_epoch = atomicAdd(&g_tick, 1u) / NBLK;

    if (blk < NCONS) {
        // ========== Consumer block: stage1 (b,k) + Wf chunk (cp,p) ==========
        const int b  = blk >> 3, k = blk & 7;
        const int cp = blk >> 2, p = blk & 3;

        // x row -> smem (aliases s4 region; sync separates uses)
        float* s_x = smem;
        if (t < FF) s_x[t] = x[b * SEQ * FF + (SEQ - 1) * FF + t];

        // issue all 8 Wf LDG.128 now; values consumed after stage1
        const float4* src4 = (const float4*)(Wf + (size_t)cp * (NNN * CC) + p * (128 * CC));
        const int c4 = t & 15;            // float4 column (c = 4*c4..)
        const int nl = t >> 4;            // 0..15
        float4 v0 = src4[(nl      ) * 16 + c4];
        float4 v1 = src4[(nl +  16) * 16 + c4];
        float4 v2 = src4[(nl +  32) * 16 + c4];
        float4 v3 = src4[(nl +  48) * 16 + c4];
        float4 v4 = src4[(nl +  64) * 16 + c4];
        float4 v5 = src4[(nl +  80) * 16 + c4];
        float4 v6 = src4[(nl +  96) * 16 + c4];
        float4 v7 = src4[(nl + 112) * 16 + c4];

        __syncthreads();

        // ---- stage1: hcat[b, k*64+h] = elu( sum_f x[f]*W_heads[k,f,h] )
        // 4 threads per h, 32 fully-unrolled loads each -> one latency window
        {
            const int h  = t >> 2;
            const int fg = t & 3;
            const float* wp = W_heads + (size_t)k * FF * HH + h;
            float acc = 0.f;
            #pragma unroll
            for (int i = 0; i < 32; ++i) {
                const int f = fg * 32 + i;
                acc = fmaf(s_x[f], wp[f * HH], acc);
            }
            acc += __shfl_down_sync(0xffffffffu, acc, 2);
            acc += __shfl_down_sync(0xffffffffu, acc, 1);
            if (fg == 0)
                g_hcat[b * (KK * HH) + k * HH + h] = acc > 0.f ? acc : expm1f(acc);
        }
        __threadfence();
        __syncthreads();
        if (t == 0) atomicAdd(&g_d1, 1u);

        // ---- Wf reduce (loads arrived long ago)
        float4 a;
        a.x = ((v0.x + v1.x) + (v2.x + v3.x)) + ((v4.x + v5.x) + (v6.x + v7.x));
        a.y = ((v0.y + v1.y) + (v2.y + v3.y)) + ((v4.y + v5.y) + (v6.y + v7.y));
        a.z = ((v0.z + v1.z) + (v2.z + v3.z)) + ((v4.z + v5.z) + (v6.z + v7.z));
        a.w = ((v0.w + v1.w) + (v2.w + v3.w)) + ((v4.w + v5.w) + (v6.w + v7.w));

        float4* s4      = (float4*)smem;          // 256 f4 (aliases s_x; sync above)
        float*  s_wpart = smem + 1024;            // 64
        float*  s_WhO   = smem + 1088;            // 2048

        s4[t] = a;
        __syncthreads();
        if (t < 128) { float4 o = s4[t + 128]; s4[t].x += o.x; s4[t].y += o.y; s4[t].z += o.z; s4[t].w += o.w; }
        __syncthreads();
        if (t < 64)  { float4 o = s4[t + 64];  s4[t].x += o.x; s4[t].y += o.y; s4[t].z += o.z; s4[t].w += o.w; }
        __syncthreads();
        if (t < 16) {
            float4 r = s4[t];
            float4 o1 = s4[t + 16], o2 = s4[t + 32], o3 = s4[t + 48];
            s_wpart[4 * t + 0] = r.x + o1.x + o2.x + o3.x;
            s_wpart[4 * t + 1] = r.y + o1.y + o2.y + o3.y;
            s_wpart[4 * t + 2] = r.z + o1.z + o2.z + o3.z;
            s_wpart[4 * t + 3] = r.w + o1.w + o2.w + o3.w;
        }
        __syncthreads();

        // ---- wait for all 32 stage-2 blocks of this epoch (backoff spin)
        if (t == 0) spin_until(&g_d2, (s_epoch + 1u) * NST2);
        __syncthreads();
        __threadfence();

        // WhO -> smem (8 KB, L2-hot)
        {
            float4* d = (float4*)s_WhO;
            const float4* s = (const float4*)g_WhO;
            d[t] = s[t];
            d[t + 256] = s[t + 256];
        }
        __syncthreads();

        // contrib[b2] = sum_c WhO[b2,c]*wpart[c]; 8 threads per b2
        {
            const int b2 = t >> 3;
            const int jg = t & 7;
            float acc = 0.f;
            #pragma unroll
            for (int i = 0; i < 8; ++i) {
                const int c = jg * 8 + i;
                acc = fmaf(s_WhO[b2 * CC + c], s_wpart[c], acc);
            }
            acc += __shfl_down_sync(0xffffffffu, acc, 4);
            acc += __shfl_down_sync(0xffffffffu, acc, 2);
            acc += __shfl_down_sync(0xffffffffu, acc, 1);
            if (jg == 0) atomicAdd(&out[b2 * CC + cp], acc);
        }
    } else {
        // ========== Stage-2 block: one batch b ==========
        const int b = blk - NCONS;

        if (t == 0) spin_until(&g_d1, (s_epoch + 1u) * NCONS);
        __syncthreads();
        __threadfence();

        float*  s_h = smem;                        // 512
        float4* s4  = (float4*)(smem + 1024);      // 256 f4

        s_h[t]       = g_hcat[b * (KK * HH) + t];
        s_h[t + 256] = g_hcat[b * (KK * HH) + 256 + t];
        __syncthreads();

        // WhO[c] = sum_j hcat[j]*W_out[j,c]; fully unrolled -> one window
        const int c4 = t & 15;
        const int g  = t >> 4;
        const float4* Wo4 = (const float4*)W_out;
        float4 a = make_float4(0.f, 0.f, 0.f, 0.f);
        #pragma unroll
        for (int jl = 0; jl < 32; ++jl) {
            const int j = g * 32 + jl;
            const float4 w = Wo4[j * 16 + c4];
            const float hv = s_h[j];
            a.x = fmaf(w.x, hv, a.x); a.y = fmaf(w.y, hv, a.y);
            a.z = fmaf(w.z, hv, a.z); a.w = fmaf(w.w, hv, a.w);
        }
        s4[t] = a;
        __syncthreads();
        if (t < 128) { float4 o = s4[t + 128]; s4[t].x += o.x; s4[t].y += o.y; s4[t].z += o.z; s4[t].w += o.w; }
        __syncthreads();
        if (t < 64)  { float4 o = s4[t + 64];  s4[t].x += o.x; s4[t].y += o.y; s4[t].z += o.z; s4[t].w += o.w; }
        __syncthreads();
        if (t < 16) {
            float4 r = s4[t];
            float4 o1 = s4[t + 16], o2 = s4[t + 32], o3 = s4[t + 48];
            r.x += o1.x + o2.x + o3.x;
            r.y += o1.y + o2.y + o3.y;
            r.z += o1.z + o2.z + o3.z;
            r.w += o1.w + o2.w + o3.w;
            ((float4*)(g_WhO + b * CC))[t] = r;
        }
        if (t < CC) out[b * CC + t] = bf[t];      // init; consumers add on top
        __threadfence();
        __syncthreads();
        if (t == 0) atomicAdd(&g_d2, 1u);
    }
}

extern "C" void kernel_launch(void* const* d_in, const int* in_sizes, int n_in,
                              void* d_out, int out_size)
{
    const float* x       = (const float*)d_in[0];
    const float* W_heads = (const float*)d_in[1];
    // d_in[2], d_in[3]: a1_heads/a2_heads — drop out (uniform softmax)
    const float* W_out   = (const float*)d_in[4];
    // d_in[5], d_in[6]: a1_out/a2_out — drop out
    const float* Wf      = (const float*)d_in[7];
    const float* bf      = (const float*)d_in[8];
    float* out           = (float*)d_out;

    gat_fused<<<NBLK, TPB>>>(x, W_heads, W_out, Wf, bf, out);
}